// round 13
// baseline (speedup 1.0000x reference)
#include <cuda_runtime.h>
#include <cuda_bf16.h>

// Problem constants
#define BB 64
#define SS 2048
#define HH 512

// Scratch (module-scope device globals; no runtime allocation)
__device__ float g_N[16 * HH];              // nest_table @ W[512:1024]
__device__ float g_G[8 * HH];               // seg_table  @ W[1024:1536]
__device__ unsigned char g_combo[BB * SS];  // (nest<<3)|seg per token
__device__ __nv_bfloat16 g_Wthi[HH * HH];   // W[0:512]^T hi (n-major, k contig)
__device__ __nv_bfloat16 g_Wtlo[HH * HH];   // W[0:512]^T lo

// ---------------------------------------------------------------------------
// Small-GEMM body: one CTA = (8 table rows) x (32-col chunk).
// ---------------------------------------------------------------------------
__device__ __forceinline__ void small_gemm_body(
    const float* __restrict__ a, const float* __restrict__ Wp,
    float* __restrict__ outp, int colbase, float* sbuf, int tid) {
    float* arow = sbuf;                       // 8*512 floats
    for (int i = tid; i < 8 * 512; i += 256) arow[i] = a[i];
    __syncthreads();

    const int c = tid & 31;
    const int kg = tid >> 5;                  // 0..7
    const int col = colbase + c;
    const float* wptr = Wp + (size_t)(kg * 64) * 512 + col;
    const float* ar = arow + kg * 64;

    float acc[8];
#pragma unroll
    for (int r = 0; r < 8; r++) acc[r] = 0.f;

#pragma unroll 1
    for (int kk = 0; kk < 64; kk += 8) {
        float w[8];
#pragma unroll
        for (int u = 0; u < 8; u++) w[u] = wptr[(size_t)(kk + u) * 512];
#pragma unroll
        for (int u = 0; u < 8; u++)
#pragma unroll
            for (int r = 0; r < 8; r++)
                acc[r] += ar[r * 512 + kk + u] * w[u];
    }

    __syncthreads();
    float* red = sbuf;                        // 8*8*32 floats
#pragma unroll
    for (int r = 0; r < 8; r++)
        red[(kg * 8 + r) * 32 + c] = acc[r];
    __syncthreads();

    {
        const int r = tid >> 5, cc = tid & 31;
        if (r < 8) {
            float s = 0.f;
#pragma unroll
            for (int g = 0; g < 8; g++) s += red[(g * 8 + r) * 32 + cc];
            outp[r * 512 + colbase + cc] = s;
        }
    }
}

// ---------------------------------------------------------------------------
// Kernel 1 "prep": 176 blocks x 256 threads.
//   [0,48):    small-table GEMMs   [48,112): W split+transpose
//   [112,176): syntax scan (warp-shuffle Lindley prefix)
// ---------------------------------------------------------------------------
__global__ void __launch_bounds__(256)
prep_kernel(const int* __restrict__ tok,
            const float* __restrict__ nest,
            const float* __restrict__ seg,
            const float* __restrict__ W) {
    __shared__ float sbuf[4160];              // 16.6 KB
    const int bid = blockIdx.x;
    const int tid = threadIdx.x;

    if (bid < 48) {
        if (bid < 32) {                       // N table, 2 row halves
            const int rh = bid >> 4;
            const int colbase = (bid & 15) * 32;
            small_gemm_body(nest + rh * 8 * 512, W + 512 * 512,
                            g_N + rh * 8 * 512, colbase, sbuf, tid);
        } else {                              // G table
            const int colbase = (bid - 32) * 32;
            small_gemm_body(seg, W + 1024 * 512, g_G, colbase, sbuf, tid);
        }
    } else if (bid < 112) {
        // ---- W[0:512] split + transpose: 8x8 tiles of 64x64 ----
        const int tb = bid - 48;
        const int ki = tb >> 3, ni = tb & 7;
        float* St = sbuf;                     // 64 x 65
#pragma unroll
        for (int l = 0; l < 4; l++) {
            const int idx = tid + l * 256;
            const int kr = idx >> 4;
            const int c4 = idx & 15;
            float4 v = *(const float4*)(W + (size_t)(ki * 64 + kr) * 512 + ni * 64 + c4 * 4);
            St[kr * 65 + c4 * 4 + 0] = v.x;
            St[kr * 65 + c4 * 4 + 1] = v.y;
            St[kr * 65 + c4 * 4 + 2] = v.z;
            St[kr * 65 + c4 * 4 + 3] = v.w;
        }
        __syncthreads();

        const int n = tid >> 2;
        const int kg = tid & 3;
        __align__(16) __nv_bfloat162 hiu[8];
        __align__(16) __nv_bfloat162 lou[8];
#pragma unroll
        for (int e = 0; e < 16; e += 2) {
            float f0 = St[(kg * 16 + e) * 65 + n];
            float f1 = St[(kg * 16 + e + 1) * 65 + n];
            __nv_bfloat16 h0 = __float2bfloat16_rn(f0);
            __nv_bfloat16 h1 = __float2bfloat16_rn(f1);
            __nv_bfloat16 l0 = __float2bfloat16_rn(f0 - __bfloat162float(h0));
            __nv_bfloat16 l1 = __float2bfloat16_rn(f1 - __bfloat162float(h1));
            hiu[e >> 1] = __nv_bfloat162(h0, h1);
            lou[e >> 1] = __nv_bfloat162(l0, l1);
        }
        const size_t off = (size_t)(ni * 64 + n) * 512 + ki * 64 + kg * 16;
        *(uint4*)(g_Wthi + off) = ((uint4*)hiu)[0];
        *(uint4*)(g_Wthi + off + 8) = ((uint4*)hiu)[1];
        *(uint4*)(g_Wtlo + off) = ((uint4*)lou)[0];
        *(uint4*)(g_Wtlo + off + 8) = ((uint4*)lou)[1];
    } else {
        // ---- syntax scan with warp-shuffle parallel prefix ----
        int* sh_tok = (int*)sbuf;
        int* wsum = (int*)sbuf + 2048;
        int* wmin = wsum + 8;
        int* wcnt = wmin + 8;

        const int b = bid - 112;
        const int* t = tok + b * SS;
        for (int i = tid; i < SS; i += 256) sh_tok[i] = t[i];
        __syncthreads();

        const int base = tid * 8;
        int s = 0, mn = 0, cnt = 0;
#pragma unroll
        for (int e = 0; e < 8; e++) {
            int tk = sh_tok[base + e];
            int op = (tk == 40) | (tk == 123) | (tk == 91);
            int cl = (tk == 41) | (tk == 125) | (tk == 93);
            s += op - cl;
            mn = min(mn, s);
            cnt += (tk > 39990);
        }

        const int lane = tid & 31;
        const int wid = tid >> 5;
        int Si = s, Mi = mn, Ci = cnt;
#pragma unroll
        for (int d = 1; d < 32; d <<= 1) {
            int So = __shfl_up_sync(0xffffffffu, Si, d);
            int Mo = __shfl_up_sync(0xffffffffu, Mi, d);
            int Co = __shfl_up_sync(0xffffffffu, Ci, d);
            if (lane >= d) { Mi = min(Mo, So + Mi); Si = So + Si; Ci = Co + Ci; }
        }
        if (lane == 31) { wsum[wid] = Si; wmin[wid] = Mi; wcnt[wid] = Ci; }

        int Se = __shfl_up_sync(0xffffffffu, Si, 1);
        int Me = __shfl_up_sync(0xffffffffu, Mi, 1);
        int Ce = __shfl_up_sync(0xffffffffu, Ci, 1);
        if (lane == 0) { Se = 0; Me = 0; Ce = 0; }
        __syncthreads();

        int Sw = 0, Mw = 0, Cw = 0;
        for (int w = 0; w < wid; w++) {
            Mw = min(Mw, Sw + wmin[w]);
            Sw += wsum[w];
            Cw += wcnt[w];
        }
        int S_pre = Sw + Se;
        int M_pre = min(Mw, Sw + Me);
        int C_pre = Cw + Ce;

        s = S_pre; mn = M_pre; cnt = C_pre;
        unsigned char* out = g_combo + b * SS + base;
#pragma unroll
        for (int e = 0; e < 8; e++) {
            int tk = sh_tok[base + e];
            int op = (tk == 40) | (tk == 123) | (tk == 91);
            int cl = (tk == 41) | (tk == 125) | (tk == 93);
            s += op - cl;
            mn = min(mn, s);
            cnt += (tk > 39990);
            int lvl = min(s - mn, 15);
            out[e] = (unsigned char)((lvl << 3) | (cnt & 7));
        }
    }
}

// ---------------------------------------------------------------------------
// Kernel 2 "mega": fused GEMM + combine, tile-level pipelined.
// 128 CTAs x 256 threads, 2 m-tiles (64x64) per CTA, BK=64, single acc.
// tileS has its OWN smem region (no aliasing): after tile0's mma the acc is
// staged to tileS once, then tile0's 64 batches stream out in 8-batch chunks
// interleaved with tile1's 8 mma k-steps. Tile1 stores at the end.
// Dynamic smem 93184 B:
//   [0,36864)      mma buffers (As_hi/As_lo/Bs_hi/Bs_lo, GSTRIDE=72)
//   [36864,54272)  tileS: 64 x 68 f32
//   [54272,89088)  NG: 128 x 68 f32 (NG[cc]=N[cc>>3]+G[cc&7], built once)
//   [89088,93184)  sc: 64 batches x 64 rows combo bytes (per m-tile)
// ---------------------------------------------------------------------------
#define GSTRIDE 72        // padded smem row stride (bf16)
#define TSTRIDE 68        // tileS/NG row stride (f32)
#define SMEM_MEGA 93184

__device__ __forceinline__ void mma_steps(
    float (&acc)[4][4],
    const __nv_bfloat16* As_hi, const __nv_bfloat16* As_lo,
    const __nv_bfloat16* Bs_hi, const __nv_bfloat16* Bs_lo,
    int wm, int wn, int r, int c) {
#pragma unroll
    for (int kk = 0; kk < 64; kk += 16) {
        unsigned int ah0, ah1, ah2, ah3, al0, al1, al2, al3;
        ah0 = *(const unsigned int*)(As_hi + (wm + r) * GSTRIDE + kk + c);
        ah1 = *(const unsigned int*)(As_hi + (wm + r + 8) * GSTRIDE + kk + c);
        ah2 = *(const unsigned int*)(As_hi + (wm + r) * GSTRIDE + kk + c + 8);
        ah3 = *(const unsigned int*)(As_hi + (wm + r + 8) * GSTRIDE + kk + c + 8);
        al0 = *(const unsigned int*)(As_lo + (wm + r) * GSTRIDE + kk + c);
        al1 = *(const unsigned int*)(As_lo + (wm + r + 8) * GSTRIDE + kk + c);
        al2 = *(const unsigned int*)(As_lo + (wm + r) * GSTRIDE + kk + c + 8);
        al3 = *(const unsigned int*)(As_lo + (wm + r + 8) * GSTRIDE + kk + c + 8);
#pragma unroll
        for (int j = 0; j < 4; j++) {
            const int n = wn + j * 8 + r;
            unsigned int bh0 = *(const unsigned int*)(Bs_hi + n * GSTRIDE + kk + c);
            unsigned int bh1 = *(const unsigned int*)(Bs_hi + n * GSTRIDE + kk + c + 8);
            unsigned int bl0 = *(const unsigned int*)(Bs_lo + n * GSTRIDE + kk + c);
            unsigned int bl1 = *(const unsigned int*)(Bs_lo + n * GSTRIDE + kk + c + 8);
            asm volatile(
                "mma.sync.aligned.m16n8k16.row.col.f32.bf16.bf16.f32 "
                "{%0,%1,%2,%3}, {%4,%5,%6,%7}, {%8,%9}, {%0,%1,%2,%3};"
                : "+f"(acc[j][0]), "+f"(acc[j][1]), "+f"(acc[j][2]), "+f"(acc[j][3])
                : "r"(ah0), "r"(ah1), "r"(ah2), "r"(ah3), "r"(bh0), "r"(bh1));
            asm volatile(
                "mma.sync.aligned.m16n8k16.row.col.f32.bf16.bf16.f32 "
                "{%0,%1,%2,%3}, {%4,%5,%6,%7}, {%8,%9}, {%0,%1,%2,%3};"
                : "+f"(acc[j][0]), "+f"(acc[j][1]), "+f"(acc[j][2]), "+f"(acc[j][3])
                : "r"(al0), "r"(al1), "r"(al2), "r"(al3), "r"(bh0), "r"(bh1));
            asm volatile(
                "mma.sync.aligned.m16n8k16.row.col.f32.bf16.bf16.f32 "
                "{%0,%1,%2,%3}, {%4,%5,%6,%7}, {%8,%9}, {%0,%1,%2,%3};"
                : "+f"(acc[j][0]), "+f"(acc[j][1]), "+f"(acc[j][2]), "+f"(acc[j][3])
                : "r"(ah0), "r"(ah1), "r"(ah2), "r"(ah3), "r"(bl0), "r"(bl1));
        }
    }
}

// Store batches [b0, b0+nb) of the 64x64 tile in tileS (R11 layout:
// thread = row x 4 float4-cols; tv re-read per call, amortized over nb).
__device__ __forceinline__ void store_batches(
    float* __restrict__ out, const float* __restrict__ tileS,
    const float* __restrict__ NG, const unsigned char* __restrict__ sc,
    int m0t, int n0, int tid, int b0, int nb) {
    const int row = tid >> 2;
    const int c4b = tid & 3;
    float4 tv[4];
#pragma unroll
    for (int k4 = 0; k4 < 4; k4++)
        tv[k4] = *(const float4*)(tileS + row * TSTRIDE + (c4b + k4 * 4) * 4);

    float4* out4 = (float4*)out;
    const unsigned rowbase = (m0t + row) * 128 + (n0 >> 2) + c4b;
#pragma unroll 2
    for (int bb = 0; bb < nb; bb++) {
        const int b = b0 + bb;
        const int cc = sc[b * 64 + row];
        const float* ngrow = NG + cc * TSTRIDE;
        const unsigned obase = b * (SS * 128u) + rowbase;
#pragma unroll
        for (int k4 = 0; k4 < 4; k4++) {
            float4 ev = *(const float4*)(ngrow + (c4b + k4 * 4) * 4);
            float4 o;
            o.x = tv[k4].x + ev.x;
            o.y = tv[k4].y + ev.y;
            o.z = tv[k4].z + ev.z;
            o.w = tv[k4].w + ev.w;
            __stcs(out4 + obase + k4 * 4, o);
        }
    }
}

__global__ void __launch_bounds__(256)
mega_kernel(const float* __restrict__ A, float* __restrict__ out) {
    extern __shared__ __align__(16) char smem_raw[];
    __nv_bfloat16* As_hi = (__nv_bfloat16*)smem_raw;
    __nv_bfloat16* As_lo = (__nv_bfloat16*)(smem_raw + 9216);
    __nv_bfloat16* Bs_hi = (__nv_bfloat16*)(smem_raw + 18432);
    __nv_bfloat16* Bs_lo = (__nv_bfloat16*)(smem_raw + 27648);
    float* tileS = (float*)(smem_raw + 36864);                 // 64 x TSTRIDE
    float* NG = (float*)(smem_raw + 54272);                    // 128 x TSTRIDE
    unsigned char* sc = (unsigned char*)(smem_raw + 89088);    // 64 x 64

    const int tid = threadIdx.x;
    const int q = blockIdx.x;            // 0..127
    const int n0 = (q >> 4) * 64;        // h band
    const int m0 = (q & 15) * 128;       // first m-tile (tile1 at m0+64)

    const int wid = tid >> 5;
    const int lane = tid & 31;
    const int wm = (wid & 3) * 16;
    const int wn = (wid >> 2) * 32;

    const int lrow = tid >> 3;
    const int lcol = (tid & 7) * 8;

    const int r = lane >> 2;
    const int c = (lane & 3) * 2;
    const int n2 = (lane & 3) * 2;

    // ---- build NG once: NG[cc][col] = N[cc>>3][n0+col] + G[cc&7][n0+col] ----
#pragma unroll
    for (int l = 0; l < 32; l++) {
        const int i = tid + l * 256;     // 0..8191
        const int cc = i >> 6;
        const int col = i & 63;
        NG[cc * TSTRIDE + col] = g_N[(cc >> 3) * 512 + n0 + col] +
                                 g_G[(cc & 7) * 512 + n0 + col];
    }

    float acc[4][4];
#pragma unroll
    for (int j = 0; j < 4; j++)
#pragma unroll
        for (int p = 0; p < 4; p++) acc[j][p] = 0.f;

    // prefetch k-step 0 of tile0
    float4 fa[4];
    uint4 wh0, wh1, wl0, wl1;
#pragma unroll
    for (int l = 0; l < 4; l++) {
        const int idx = tid + l * 256;
        fa[l] = *(const float4*)(A + (size_t)(m0 + (idx >> 4)) * 512 + (idx & 15) * 4);
    }
    wh0 = *(const uint4*)(g_Wthi + (size_t)(n0 + lrow) * 512 + lcol);
    wh1 = *(const uint4*)(g_Wthi + (size_t)(n0 + lrow + 32) * 512 + lcol);
    wl0 = *(const uint4*)(g_Wtlo + (size_t)(n0 + lrow) * 512 + lcol);
    wl1 = *(const uint4*)(g_Wtlo + (size_t)(n0 + lrow + 32) * 512 + lcol);

#pragma unroll 1
    for (int t = 0; t < 16; t++) {
        __syncthreads();   // orders tileS/sc staging (t==8) and smem reuse
        // stage A (split f32 -> hi/lo bf16 in-register) and W tiles
#pragma unroll
        for (int l = 0; l < 4; l++) {
            const int idx = tid + l * 256;
            const int arow = idx >> 4;
            const int ac = (idx & 15) * 4;
            float4 v = fa[l];
            __nv_bfloat16 hx = __float2bfloat16_rn(v.x);
            __nv_bfloat16 hy = __float2bfloat16_rn(v.y);
            __nv_bfloat16 hz = __float2bfloat16_rn(v.z);
            __nv_bfloat16 hw = __float2bfloat16_rn(v.w);
            *(__nv_bfloat162*)(As_hi + arow * GSTRIDE + ac) = __nv_bfloat162(hx, hy);
            *(__nv_bfloat162*)(As_hi + arow * GSTRIDE + ac + 2) = __nv_bfloat162(hz, hw);
            __nv_bfloat16 lx = __float2bfloat16_rn(v.x - __bfloat162float(hx));
            __nv_bfloat16 ly = __float2bfloat16_rn(v.y - __bfloat162float(hy));
            __nv_bfloat16 lz = __float2bfloat16_rn(v.z - __bfloat162float(hz));
            __nv_bfloat16 lw = __float2bfloat16_rn(v.w - __bfloat162float(hw));
            *(__nv_bfloat162*)(As_lo + arow * GSTRIDE + ac) = __nv_bfloat162(lx, ly);
            *(__nv_bfloat162*)(As_lo + arow * GSTRIDE + ac + 2) = __nv_bfloat162(lz, lw);
        }
        *(uint4*)(Bs_hi + lrow * GSTRIDE + lcol) = wh0;
        *(uint4*)(Bs_hi + (lrow + 32) * GSTRIDE + lcol) = wh1;
        *(uint4*)(Bs_lo + lrow * GSTRIDE + lcol) = wl0;
        *(uint4*)(Bs_lo + (lrow + 32) * GSTRIDE + lcol) = wl1;
        __syncthreads();

        if (t < 15) {
            const int tn = t + 1;
            const int mrow = m0 + (tn >> 3) * 64;
            const int k0 = (tn & 7) * 64;
#pragma unroll
            for (int l = 0; l < 4; l++) {
                const int idx = tid + l * 256;
                fa[l] = *(const float4*)(A + (size_t)(mrow + (idx >> 4)) * 512 + k0 + (idx & 15) * 4);
            }
            wh0 = *(const uint4*)(g_Wthi + (size_t)(n0 + lrow) * 512 + k0 + lcol);
            wh1 = *(const uint4*)(g_Wthi + (size_t)(n0 + lrow + 32) * 512 + k0 + lcol);
            wl0 = *(const uint4*)(g_Wtlo + (size_t)(n0 + lrow) * 512 + k0 + lcol);
            wl1 = *(const uint4*)(g_Wtlo + (size_t)(n0 + lrow + 32) * 512 + k0 + lcol);
        }

        mma_steps(acc, As_hi, As_lo, Bs_hi, Bs_lo, wm, wn, r, c);

        if (t == 7) {
            // tile0 mma complete: stage acc -> tileS, load tile0 combo, reset
#pragma unroll
            for (int j = 0; j < 4; j++) {
                *(float2*)(tileS + (wm + r) * TSTRIDE + wn + j * 8 + n2) =
                    make_float2(acc[j][0], acc[j][1]);
                *(float2*)(tileS + (wm + r + 8) * TSTRIDE + wn + j * 8 + n2) =
                    make_float2(acc[j][2], acc[j][3]);
            }
            {
                const int b = tid >> 2;
                const int part = tid & 3;
                *(uint4*)(sc + b * 64 + part * 16) =
                    *(const uint4*)(g_combo + b * SS + m0 + part * 16);
            }
#pragma unroll
            for (int j = 0; j < 4; j++)
#pragma unroll
                for (int p = 0; p < 4; p++) acc[j][p] = 0.f;
            // next iteration's top __syncthreads orders this staging
        } else if (t >= 8) {
            // overlap: stream 8 batches of tile0 while tile1's mma proceeds
            store_batches(out, tileS, NG, sc, m0, n0, tid, (t - 8) * 8, 8);
        }
    }

    // ---- tile1 epilogue ----
    __syncthreads();            // all tile0 tileS/sc reads done
#pragma unroll
    for (int j = 0; j < 4; j++) {
        *(float2*)(tileS + (wm + r) * TSTRIDE + wn + j * 8 + n2) =
            make_float2(acc[j][0], acc[j][1]);
        *(float2*)(tileS + (wm + r + 8) * TSTRIDE + wn + j * 8 + n2) =
            make_float2(acc[j][2], acc[j][3]);
    }
    {
        const int b = tid >> 2;
        const int part = tid & 3;
        *(uint4*)(sc + b * 64 + part * 16) =
            *(const uint4*)(g_combo + b * SS + m0 + 64 + part * 16);
    }
    __syncthreads();
    store_batches(out, tileS, NG, sc, m0 + 64, n0, tid, 0, 64);
}

// ---------------------------------------------------------------------------
extern "C" void kernel_launch(void* const* d_in, const int* in_sizes, int n_in,
                              void* d_out, int out_size) {
    const int*   tok  = (const int*)d_in[0];    // token_ids [64,2048] int32
    const float* pos  = (const float*)d_in[1];  // pos_table [2048,512]
    const float* nest = (const float*)d_in[2];  // nest_table [16,512]
    const float* seg  = (const float*)d_in[3];  // seg_table [8,512]
    const float* W    = (const float*)d_in[4];  // W [1536,512]
    float* out = (float*)d_out;                 // [64,2048,512] f32

    cudaFuncSetAttribute(mega_kernel,
                         cudaFuncAttributeMaxDynamicSharedMemorySize, SMEM_MEGA);

    prep_kernel<<<176, 256>>>(tok, nest, seg, W);
    mega_kernel<<<128, 256, SMEM_MEGA>>>(pos, out);
}

// round 14
// speedup vs baseline: 1.0816x; 1.0816x over previous
#include <cuda_runtime.h>
#include <cuda_bf16.h>

// Problem constants
#define BB 64
#define SS 2048
#define HH 512

// Scratch (module-scope device globals; no runtime allocation)
__device__ float g_N[16 * HH];              // nest_table @ W[512:1024]
__device__ float g_G[8 * HH];               // seg_table  @ W[1024:1536]
__device__ unsigned char g_combo[BB * SS];  // (nest<<3)|seg per token
__device__ __nv_bfloat16 g_Wthi[HH * HH];   // W[0:512]^T hi (n-major, k contig)
__device__ __nv_bfloat16 g_Wtlo[HH * HH];   // W[0:512]^T lo

// ---------------------------------------------------------------------------
// Small-GEMM body: one CTA = (8 table rows) x (32-col chunk).
// ---------------------------------------------------------------------------
__device__ __forceinline__ void small_gemm_body(
    const float* __restrict__ a, const float* __restrict__ Wp,
    float* __restrict__ outp, int colbase, float* sbuf, int tid) {
    float* arow = sbuf;                       // 8*512 floats
    for (int i = tid; i < 8 * 512; i += 256) arow[i] = a[i];
    __syncthreads();

    const int c = tid & 31;
    const int kg = tid >> 5;                  // 0..7
    const int col = colbase + c;
    const float* wptr = Wp + (size_t)(kg * 64) * 512 + col;
    const float* ar = arow + kg * 64;

    float acc[8];
#pragma unroll
    for (int r = 0; r < 8; r++) acc[r] = 0.f;

#pragma unroll 1
    for (int kk = 0; kk < 64; kk += 8) {
        float w[8];
#pragma unroll
        for (int u = 0; u < 8; u++) w[u] = wptr[(size_t)(kk + u) * 512];
#pragma unroll
        for (int u = 0; u < 8; u++)
#pragma unroll
            for (int r = 0; r < 8; r++)
                acc[r] += ar[r * 512 + kk + u] * w[u];
    }

    __syncthreads();
    float* red = sbuf;                        // 8*8*32 floats
#pragma unroll
    for (int r = 0; r < 8; r++)
        red[(kg * 8 + r) * 32 + c] = acc[r];
    __syncthreads();

    {
        const int r = tid >> 5, cc = tid & 31;
        if (r < 8) {
            float s = 0.f;
#pragma unroll
            for (int g = 0; g < 8; g++) s += red[(g * 8 + r) * 32 + cc];
            outp[r * 512 + colbase + cc] = s;
        }
    }
}

// ---------------------------------------------------------------------------
// Kernel 1 "prep": 176 blocks x 256 threads.
//   [0,48):    small-table GEMMs   [48,112): W split+transpose
//   [112,176): syntax scan (warp-shuffle Lindley prefix)
// ---------------------------------------------------------------------------
__global__ void __launch_bounds__(256)
prep_kernel(const int* __restrict__ tok,
            const float* __restrict__ nest,
            const float* __restrict__ seg,
            const float* __restrict__ W) {
    __shared__ float sbuf[4160];              // 16.6 KB
    const int bid = blockIdx.x;
    const int tid = threadIdx.x;

    if (bid < 48) {
        if (bid < 32) {                       // N table, 2 row halves
            const int rh = bid >> 4;
            const int colbase = (bid & 15) * 32;
            small_gemm_body(nest + rh * 8 * 512, W + 512 * 512,
                            g_N + rh * 8 * 512, colbase, sbuf, tid);
        } else {                              // G table
            const int colbase = (bid - 32) * 32;
            small_gemm_body(seg, W + 1024 * 512, g_G, colbase, sbuf, tid);
        }
    } else if (bid < 112) {
        // ---- W[0:512] split + transpose: 8x8 tiles of 64x64 ----
        const int tb = bid - 48;
        const int ki = tb >> 3, ni = tb & 7;
        float* St = sbuf;                     // 64 x 65
#pragma unroll
        for (int l = 0; l < 4; l++) {
            const int idx = tid + l * 256;
            const int kr = idx >> 4;
            const int c4 = idx & 15;
            float4 v = *(const float4*)(W + (size_t)(ki * 64 + kr) * 512 + ni * 64 + c4 * 4);
            St[kr * 65 + c4 * 4 + 0] = v.x;
            St[kr * 65 + c4 * 4 + 1] = v.y;
            St[kr * 65 + c4 * 4 + 2] = v.z;
            St[kr * 65 + c4 * 4 + 3] = v.w;
        }
        __syncthreads();

        const int n = tid >> 2;
        const int kg = tid & 3;
        __align__(16) __nv_bfloat162 hiu[8];
        __align__(16) __nv_bfloat162 lou[8];
#pragma unroll
        for (int e = 0; e < 16; e += 2) {
            float f0 = St[(kg * 16 + e) * 65 + n];
            float f1 = St[(kg * 16 + e + 1) * 65 + n];
            __nv_bfloat16 h0 = __float2bfloat16_rn(f0);
            __nv_bfloat16 h1 = __float2bfloat16_rn(f1);
            __nv_bfloat16 l0 = __float2bfloat16_rn(f0 - __bfloat162float(h0));
            __nv_bfloat16 l1 = __float2bfloat16_rn(f1 - __bfloat162float(h1));
            hiu[e >> 1] = __nv_bfloat162(h0, h1);
            lou[e >> 1] = __nv_bfloat162(l0, l1);
        }
        const size_t off = (size_t)(ni * 64 + n) * 512 + ki * 64 + kg * 16;
        *(uint4*)(g_Wthi + off) = ((uint4*)hiu)[0];
        *(uint4*)(g_Wthi + off + 8) = ((uint4*)hiu)[1];
        *(uint4*)(g_Wtlo + off) = ((uint4*)lou)[0];
        *(uint4*)(g_Wtlo + off + 8) = ((uint4*)lou)[1];
    } else {
        // ---- syntax scan with warp-shuffle parallel prefix ----
        int* sh_tok = (int*)sbuf;
        int* wsum = (int*)sbuf + 2048;
        int* wmin = wsum + 8;
        int* wcnt = wmin + 8;

        const int b = bid - 112;
        const int* t = tok + b * SS;
        for (int i = tid; i < SS; i += 256) sh_tok[i] = t[i];
        __syncthreads();

        const int base = tid * 8;
        int s = 0, mn = 0, cnt = 0;
#pragma unroll
        for (int e = 0; e < 8; e++) {
            int tk = sh_tok[base + e];
            int op = (tk == 40) | (tk == 123) | (tk == 91);
            int cl = (tk == 41) | (tk == 125) | (tk == 93);
            s += op - cl;
            mn = min(mn, s);
            cnt += (tk > 39990);
        }

        const int lane = tid & 31;
        const int wid = tid >> 5;
        int Si = s, Mi = mn, Ci = cnt;
#pragma unroll
        for (int d = 1; d < 32; d <<= 1) {
            int So = __shfl_up_sync(0xffffffffu, Si, d);
            int Mo = __shfl_up_sync(0xffffffffu, Mi, d);
            int Co = __shfl_up_sync(0xffffffffu, Ci, d);
            if (lane >= d) { Mi = min(Mo, So + Mi); Si = So + Si; Ci = Co + Ci; }
        }
        if (lane == 31) { wsum[wid] = Si; wmin[wid] = Mi; wcnt[wid] = Ci; }

        int Se = __shfl_up_sync(0xffffffffu, Si, 1);
        int Me = __shfl_up_sync(0xffffffffu, Mi, 1);
        int Ce = __shfl_up_sync(0xffffffffu, Ci, 1);
        if (lane == 0) { Se = 0; Me = 0; Ce = 0; }
        __syncthreads();

        int Sw = 0, Mw = 0, Cw = 0;
        for (int w = 0; w < wid; w++) {
            Mw = min(Mw, Sw + wmin[w]);
            Sw += wsum[w];
            Cw += wcnt[w];
        }
        int S_pre = Sw + Se;
        int M_pre = min(Mw, Sw + Me);
        int C_pre = Cw + Ce;

        s = S_pre; mn = M_pre; cnt = C_pre;
        unsigned char* out = g_combo + b * SS + base;
#pragma unroll
        for (int e = 0; e < 8; e++) {
            int tk = sh_tok[base + e];
            int op = (tk == 40) | (tk == 123) | (tk == 91);
            int cl = (tk == 41) | (tk == 125) | (tk == 93);
            s += op - cl;
            mn = min(mn, s);
            cnt += (tk > 39990);
            int lvl = min(s - mn, 15);
            out[e] = (unsigned char)((lvl << 3) | (cnt & 7));
        }
    }
}

// ---------------------------------------------------------------------------
// Kernel 2 "mega": fused GEMM + combine, ONE 64x64 tile per CTA, grid 256.
// smem/CTA = 75776 B -> TWO CTAs co-resident per SM; the scheduler naturally
// overlaps one CTA's mma phase with its neighbor's store phase (inter-CTA
// pipelining, replacing the failed intra-CTA variants).
// Dynamic smem 75776 B:
//   [0,36864)      mma buffers (As_hi/As_lo/Bs_hi/Bs_lo, GSTRIDE=72)
//                  -- aliased by tileS (64 x 68 f32) in the epilogue
//   [36864,71680)  NG: 128 x 68 f32 (persistent; NG[cc]=N[cc>>3]+G[cc&7])
//   [71680,75776)  sc: 64 batches x 64 rows combo bytes
// ---------------------------------------------------------------------------
#define GSTRIDE 72        // padded smem row stride (bf16)
#define TSTRIDE 68        // tileS/NG row stride (f32)
#define SMEM_MEGA 75776

__device__ __forceinline__ void mma_steps(
    float (&acc)[4][4],
    const __nv_bfloat16* As_hi, const __nv_bfloat16* As_lo,
    const __nv_bfloat16* Bs_hi, const __nv_bfloat16* Bs_lo,
    int wm, int wn, int r, int c) {
#pragma unroll
    for (int kk = 0; kk < 64; kk += 16) {
        unsigned int ah0, ah1, ah2, ah3, al0, al1, al2, al3;
        ah0 = *(const unsigned int*)(As_hi + (wm + r) * GSTRIDE + kk + c);
        ah1 = *(const unsigned int*)(As_hi + (wm + r + 8) * GSTRIDE + kk + c);
        ah2 = *(const unsigned int*)(As_hi + (wm + r) * GSTRIDE + kk + c + 8);
        ah3 = *(const unsigned int*)(As_hi + (wm + r + 8) * GSTRIDE + kk + c + 8);
        al0 = *(const unsigned int*)(As_lo + (wm + r) * GSTRIDE + kk + c);
        al1 = *(const unsigned int*)(As_lo + (wm + r + 8) * GSTRIDE + kk + c);
        al2 = *(const unsigned int*)(As_lo + (wm + r) * GSTRIDE + kk + c + 8);
        al3 = *(const unsigned int*)(As_lo + (wm + r + 8) * GSTRIDE + kk + c + 8);
#pragma unroll
        for (int j = 0; j < 4; j++) {
            const int n = wn + j * 8 + r;
            unsigned int bh0 = *(const unsigned int*)(Bs_hi + n * GSTRIDE + kk + c);
            unsigned int bh1 = *(const unsigned int*)(Bs_hi + n * GSTRIDE + kk + c + 8);
            unsigned int bl0 = *(const unsigned int*)(Bs_lo + n * GSTRIDE + kk + c);
            unsigned int bl1 = *(const unsigned int*)(Bs_lo + n * GSTRIDE + kk + c + 8);
            asm volatile(
                "mma.sync.aligned.m16n8k16.row.col.f32.bf16.bf16.f32 "
                "{%0,%1,%2,%3}, {%4,%5,%6,%7}, {%8,%9}, {%0,%1,%2,%3};"
                : "+f"(acc[j][0]), "+f"(acc[j][1]), "+f"(acc[j][2]), "+f"(acc[j][3])
                : "r"(ah0), "r"(ah1), "r"(ah2), "r"(ah3), "r"(bh0), "r"(bh1));
            asm volatile(
                "mma.sync.aligned.m16n8k16.row.col.f32.bf16.bf16.f32 "
                "{%0,%1,%2,%3}, {%4,%5,%6,%7}, {%8,%9}, {%0,%1,%2,%3};"
                : "+f"(acc[j][0]), "+f"(acc[j][1]), "+f"(acc[j][2]), "+f"(acc[j][3])
                : "r"(al0), "r"(al1), "r"(al2), "r"(al3), "r"(bh0), "r"(bh1));
            asm volatile(
                "mma.sync.aligned.m16n8k16.row.col.f32.bf16.bf16.f32 "
                "{%0,%1,%2,%3}, {%4,%5,%6,%7}, {%8,%9}, {%0,%1,%2,%3};"
                : "+f"(acc[j][0]), "+f"(acc[j][1]), "+f"(acc[j][2]), "+f"(acc[j][3])
                : "r"(ah0), "r"(ah1), "r"(ah2), "r"(ah3), "r"(bl0), "r"(bl1));
        }
    }
}

__global__ void __launch_bounds__(256)
mega_kernel(const float* __restrict__ A, float* __restrict__ out) {
    extern __shared__ __align__(16) char smem_raw[];
    __nv_bfloat16* As_hi = (__nv_bfloat16*)smem_raw;
    __nv_bfloat16* As_lo = (__nv_bfloat16*)(smem_raw + 9216);
    __nv_bfloat16* Bs_hi = (__nv_bfloat16*)(smem_raw + 18432);
    __nv_bfloat16* Bs_lo = (__nv_bfloat16*)(smem_raw + 27648);
    float* NG = (float*)(smem_raw + 36864);                    // 128 x TSTRIDE
    unsigned char* sc = (unsigned char*)(smem_raw + 71680);    // 64 x 64

    const int tid = threadIdx.x;
    const int q = blockIdx.x;            // 0..255
    const int n0 = (q >> 5) * 64;        // h band (0..7)
    const int m0t = (q & 31) * 64;       // m tile (0..31)

    const int wid = tid >> 5;
    const int lane = tid & 31;
    const int wm = (wid & 3) * 16;
    const int wn = (wid >> 2) * 32;

    const int lrow = tid >> 3;
    const int lcol = (tid & 7) * 8;

    const int r = lane >> 2;
    const int c = (lane & 3) * 2;
    const int n2 = (lane & 3) * 2;

    // ---- build NG once: NG[cc][col] = N[cc>>3][n0+col] + G[cc&7][n0+col] ----
#pragma unroll
    for (int l = 0; l < 32; l++) {
        const int i = tid + l * 256;     // 0..8191
        const int cc = i >> 6;
        const int col = i & 63;
        NG[cc * TSTRIDE + col] = g_N[(cc >> 3) * 512 + n0 + col] +
                                 g_G[(cc & 7) * 512 + n0 + col];
    }

    float acc[4][4];
#pragma unroll
    for (int j = 0; j < 4; j++)
#pragma unroll
        for (int p = 0; p < 4; p++) acc[j][p] = 0.f;

    // prefetch k-step 0
    float4 fa[4];
    uint4 wh0, wh1, wl0, wl1;
#pragma unroll
    for (int l = 0; l < 4; l++) {
        const int idx = tid + l * 256;
        fa[l] = *(const float4*)(A + (size_t)(m0t + (idx >> 4)) * 512 + (idx & 15) * 4);
    }
    wh0 = *(const uint4*)(g_Wthi + (size_t)(n0 + lrow) * 512 + lcol);
    wh1 = *(const uint4*)(g_Wthi + (size_t)(n0 + lrow + 32) * 512 + lcol);
    wl0 = *(const uint4*)(g_Wtlo + (size_t)(n0 + lrow) * 512 + lcol);
    wl1 = *(const uint4*)(g_Wtlo + (size_t)(n0 + lrow + 32) * 512 + lcol);

#pragma unroll 1
    for (int t = 0; t < 8; t++) {
        __syncthreads();
        // stage A (split f32 -> hi/lo bf16 in-register) and W tiles
#pragma unroll
        for (int l = 0; l < 4; l++) {
            const int idx = tid + l * 256;
            const int arow = idx >> 4;
            const int ac = (idx & 15) * 4;
            float4 v = fa[l];
            __nv_bfloat16 hx = __float2bfloat16_rn(v.x);
            __nv_bfloat16 hy = __float2bfloat16_rn(v.y);
            __nv_bfloat16 hz = __float2bfloat16_rn(v.z);
            __nv_bfloat16 hw = __float2bfloat16_rn(v.w);
            *(__nv_bfloat162*)(As_hi + arow * GSTRIDE + ac) = __nv_bfloat162(hx, hy);
            *(__nv_bfloat162*)(As_hi + arow * GSTRIDE + ac + 2) = __nv_bfloat162(hz, hw);
            __nv_bfloat16 lx = __float2bfloat16_rn(v.x - __bfloat162float(hx));
            __nv_bfloat16 ly = __float2bfloat16_rn(v.y - __bfloat162float(hy));
            __nv_bfloat16 lz = __float2bfloat16_rn(v.z - __bfloat162float(hz));
            __nv_bfloat16 lw = __float2bfloat16_rn(v.w - __bfloat162float(hw));
            *(__nv_bfloat162*)(As_lo + arow * GSTRIDE + ac) = __nv_bfloat162(lx, ly);
            *(__nv_bfloat162*)(As_lo + arow * GSTRIDE + ac + 2) = __nv_bfloat162(lz, lw);
        }
        *(uint4*)(Bs_hi + lrow * GSTRIDE + lcol) = wh0;
        *(uint4*)(Bs_hi + (lrow + 32) * GSTRIDE + lcol) = wh1;
        *(uint4*)(Bs_lo + lrow * GSTRIDE + lcol) = wl0;
        *(uint4*)(Bs_lo + (lrow + 32) * GSTRIDE + lcol) = wl1;
        __syncthreads();

        if (t < 7) {
            const int k0 = (t + 1) * 64;
#pragma unroll
            for (int l = 0; l < 4; l++) {
                const int idx = tid + l * 256;
                fa[l] = *(const float4*)(A + (size_t)(m0t + (idx >> 4)) * 512 + k0 + (idx & 15) * 4);
            }
            wh0 = *(const uint4*)(g_Wthi + (size_t)(n0 + lrow) * 512 + k0 + lcol);
            wh1 = *(const uint4*)(g_Wthi + (size_t)(n0 + lrow + 32) * 512 + k0 + lcol);
            wl0 = *(const uint4*)(g_Wtlo + (size_t)(n0 + lrow) * 512 + k0 + lcol);
            wl1 = *(const uint4*)(g_Wtlo + (size_t)(n0 + lrow + 32) * 512 + k0 + lcol);
        }

        mma_steps(acc, As_hi, As_lo, Bs_hi, Bs_lo, wm, wn, r, c);
    }

    // ---------------- epilogue ----------------
    __syncthreads();            // mma smem reads done; tileS aliases As

    float* tileS = (float*)smem_raw;                       // 64 x TSTRIDE

    // stage acc tile + combo slice
#pragma unroll
    for (int j = 0; j < 4; j++) {
        *(float2*)(tileS + (wm + r) * TSTRIDE + wn + j * 8 + n2) =
            make_float2(acc[j][0], acc[j][1]);
        *(float2*)(tileS + (wm + r + 8) * TSTRIDE + wn + j * 8 + n2) =
            make_float2(acc[j][2], acc[j][3]);
    }
    {
        const int b = tid >> 2;
        const int part = tid & 3;
        *(uint4*)(sc + b * 64 + part * 16) =
            *(const uint4*)(g_combo + b * SS + m0t + part * 16);
    }
    __syncthreads();

    // re-partition: thread = (row = tid>>2) x 4 float4 cols
    const int row = tid >> 2;
    const int c4b = tid & 3;
    float4 tv[4];
#pragma unroll
    for (int k4 = 0; k4 < 4; k4++)
        tv[k4] = *(const float4*)(tileS + row * TSTRIDE + (c4b + k4 * 4) * 4);

    float4* out4 = (float4*)out;
    const unsigned rowbase = (m0t + row) * 128 + (n0 >> 2) + c4b;
#pragma unroll 2
    for (int b = 0; b < BB; b++) {
        const int cc = sc[b * 64 + row];
        const float* ngrow = NG + cc * TSTRIDE;
        const unsigned obase = b * (SS * 128u) + rowbase;
#pragma unroll
        for (int k4 = 0; k4 < 4; k4++) {
            float4 ev = *(const float4*)(ngrow + (c4b + k4 * 4) * 4);
            float4 o;
            o.x = tv[k4].x + ev.x;
            o.y = tv[k4].y + ev.y;
            o.z = tv[k4].z + ev.z;
            o.w = tv[k4].w + ev.w;
            __stcs(out4 + obase + k4 * 4, o);
        }
    }
}

// ---------------------------------------------------------------------------
extern "C" void kernel_launch(void* const* d_in, const int* in_sizes, int n_in,
                              void* d_out, int out_size) {
    const int*   tok  = (const int*)d_in[0];    // token_ids [64,2048] int32
    const float* pos  = (const float*)d_in[1];  // pos_table [2048,512]
    const float* nest = (const float*)d_in[2];  // nest_table [16,512]
    const float* seg  = (const float*)d_in[3];  // seg_table [8,512]
    const float* W    = (const float*)d_in[4];  // W [1536,512]
    float* out = (float*)d_out;                 // [64,2048,512] f32

    cudaFuncSetAttribute(mega_kernel,
                         cudaFuncAttributeMaxDynamicSharedMemorySize, SMEM_MEGA);

    prep_kernel<<<176, 256>>>(tok, nest, seg, W);
    mega_kernel<<<256, 256, SMEM_MEGA>>>(pos, out);
}